// round 3
// baseline (speedup 1.0000x reference)
#include <cuda_runtime.h>
#include <cuda_bf16.h>
#include <cstdint>

#define DIN   2048
#define DOUT  2048
#define MTOT  8192

// ---------------- scratch (static device globals; no allocation) ----------------
__device__ int8_t g_xq[(size_t)MTOT * DIN];   // quantized activations, [M][K] int8
__device__ int8_t g_wt[(size_t)DOUT * DIN];   // W transposed+quantized, [N][K] int8

// ---------------- helpers ----------------
__device__ __forceinline__ uint32_t smem_u32(const void* p) {
    uint32_t a;
    asm("{ .reg .u64 t; cvta.to.shared.u64 t, %1; cvt.u32.u64 %0, t; }" : "=r"(a) : "l"(p));
    return a;
}

#define CP_ASYNC16(dst, src) \
    asm volatile("cp.async.cg.shared.global [%0], [%1], 16;" :: "r"(dst), "l"(src) : "memory")
#define CP_ASYNC_COMMIT() asm volatile("cp.async.commit_group;" ::: "memory")
#define CP_ASYNC_WAIT(n)  asm volatile("cp.async.wait_group %0;" :: "n"(n) : "memory")

#define LDSM_X4(r0, r1, r2, r3, addr) \
    asm volatile("ldmatrix.sync.aligned.m8n8.x4.shared.b16 {%0,%1,%2,%3}, [%4];" \
                 : "=r"(r0), "=r"(r1), "=r"(r2), "=r"(r3) : "r"(addr))

__device__ __forceinline__ void imma_16832(int* c, uint32_t a0, uint32_t a1, uint32_t a2, uint32_t a3,
                                           uint32_t b0, uint32_t b1) {
    asm volatile(
        "mma.sync.aligned.m16n8k32.row.col.s32.s8.s8.s32 "
        "{%0,%1,%2,%3}, {%4,%5,%6,%7}, {%8,%9}, {%0,%1,%2,%3};"
        : "+r"(c[0]), "+r"(c[1]), "+r"(c[2]), "+r"(c[3])
        : "r"(a0), "r"(a1), "r"(a2), "r"(a3), "r"(b0), "r"(b1));
}

// ---------------- pre-pass 1: quantize x -> int8 ----------------
__global__ void quant_x_kernel(const float* __restrict__ x, const float* __restrict__ scale_p) {
    const float inv_s = 1.0f / fmaxf(scale_p[0], 1e-8f);
    const int i = blockIdx.x * blockDim.x + threadIdx.x;   // 0 .. M*K/16-1
    const float4* xin = reinterpret_cast<const float4*>(x) + (size_t)i * 4;
    int packed[4];
    #pragma unroll
    for (int j = 0; j < 4; j++) {
        float4 v = xin[j];
        int q0 = __float2int_rn(fminf(fmaxf(v.x * inv_s, -127.f), 127.f));
        int q1 = __float2int_rn(fminf(fmaxf(v.y * inv_s, -127.f), 127.f));
        int q2 = __float2int_rn(fminf(fmaxf(v.z * inv_s, -127.f), 127.f));
        int q3 = __float2int_rn(fminf(fmaxf(v.w * inv_s, -127.f), 127.f));
        packed[j] = (q0 & 0xFF) | ((q1 & 0xFF) << 8) | ((q2 & 0xFF) << 16) | (q3 << 24);
    }
    reinterpret_cast<int4*>(g_xq)[i] = make_int4(packed[0], packed[1], packed[2], packed[3]);
}

// ---------------- pre-pass 2: transpose + quantize W -> int8 [N][K], coalesced stores ----------------
// Block (32,8): tile n:32 (blockIdx.x) x k:128 (blockIdx.y). Stores are full 128B rows.
__global__ void conv_wt_kernel(const float* __restrict__ w) {
    __shared__ float t[128][33];     // [k][n]
    const int bx = blockIdx.x * 32;   // n tile
    const int by = blockIdx.y * 128;  // k tile
    const int tx = threadIdx.x;       // 0..31
    const int ty = threadIdx.y;       // 0..7
    #pragma unroll
    for (int i = ty; i < 128; i += 8)
        t[i][tx] = w[(size_t)(by + i) * DOUT + bx + tx];   // coalesced 128B reads
    __syncthreads();
    // warp ty writes n rows {ty, ty+8, ty+16, ty+24}; lane tx covers k = tx*4..tx*4+3
    #pragma unroll
    for (int r = 0; r < 4; r++) {
        const int n = ty + r * 8;
        char4 c;
        c.x = (char)__float2int_rn(t[tx * 4 + 0][n]);
        c.y = (char)__float2int_rn(t[tx * 4 + 1][n]);
        c.z = (char)__float2int_rn(t[tx * 4 + 2][n]);
        c.w = (char)__float2int_rn(t[tx * 4 + 3][n]);
        *reinterpret_cast<char4*>(&g_wt[(size_t)(bx + n) * DIN + by + tx * 4]) = c;  // 128B/warp
    }
}

// ---------------- GEMM: out[M,N] = xq @ wt^T + bias (int8 IMMA, 128x256x64, ldmatrix) ----------------
#define BM 128
#define BN 256
#define BK 64
#define STAGES 3
#define NTHREADS 256
#define NCHUNKS (DIN / BK)        // 32

#define ROW_PITCH 80                         // 64B data + 16B pad: LDSM phases conflict-free
#define A_STAGE   (BM * ROW_PITCH)           // 10240
#define B_STAGE   (BN * ROW_PITCH)           // 20480
#define STAGE_BYTES (A_STAGE + B_STAGE)      // 30720
#define SMEM_TOTAL (STAGES * STAGE_BYTES)    // 92160

__global__ void __launch_bounds__(NTHREADS, 1) gemm_kernel(const float* __restrict__ bias,
                                                           float* __restrict__ out) {
    extern __shared__ __align__(128) char smem[];
    const uint32_t smem_base = smem_u32(smem);

    const int tid  = threadIdx.x;
    const int wid  = tid >> 5;
    const int lane = tid & 31;
    const int wm   = wid >> 2;        // 0..1 : 64-row M half
    const int wn   = wid & 3;         // 0..3 : 64-col N quarter
    const int g    = lane >> 2;
    const int tg   = lane & 3;

    const int8_t* Arow = g_xq + (size_t)blockIdx.y * BM * DIN;
    const int8_t* Brow = g_wt + (size_t)blockIdx.x * BN * DIN;

    // -------- async stage loader: 384 rows x 64B = 1536 16B-vectors / 256 thr = 6 each --------
    auto load_stage = [&](int stage, int chunk) {
        const int k0 = chunk * BK;
        const uint32_t base = smem_base + stage * STAGE_BYTES;
        #pragma unroll
        for (int j = 0; j < 6; j++) {
            const int v   = tid + j * 256;
            const int r   = v >> 2;
            const int c16 = (v & 3) * 16;
            if (r < BM) {
                CP_ASYNC16(base + r * ROW_PITCH + c16, Arow + (size_t)r * DIN + k0 + c16);
            } else {
                const int r2 = r - BM;
                CP_ASYNC16(base + A_STAGE + r2 * ROW_PITCH + c16, Brow + (size_t)r2 * DIN + k0 + c16);
            }
        }
    };

    int acc[4][8][4];
    #pragma unroll
    for (int mi = 0; mi < 4; mi++)
        #pragma unroll
        for (int ni = 0; ni < 8; ni++)
            #pragma unroll
            for (int q = 0; q < 4; q++) acc[mi][ni][q] = 0;

    #pragma unroll
    for (int s = 0; s < STAGES - 1; s++) {
        load_stage(s, s);
        CP_ASYNC_COMMIT();
    }

    // ldmatrix per-lane base addresses (stage-relative)
    // A x4: matrices = rows {0-7,8-15}@ko, {0-7,8-15}@ko+16 within a 16-row mi block
    const uint32_t aOff = (uint32_t)(wm * 64 + (lane & 15)) * ROW_PITCH + ((lane >> 4) * 16);
    // B x4: matrices = cols {0-7}@ko, {0-7}@ko+16, {8-15}@ko, {8-15}@ko+16 within a 16-col pair
    const uint32_t bOff = (uint32_t)(wn * 64 + (lane & 7) + ((lane >> 4) << 3)) * ROW_PITCH
                          + ((lane & 8) ? 16u : 0u);

    for (int c = 0; c < NCHUNKS; c++) {
        CP_ASYNC_WAIT(STAGES - 2);
        __syncthreads();

        if (c + STAGES - 1 < NCHUNKS) load_stage((c + STAGES - 1) % STAGES, c + STAGES - 1);
        CP_ASYNC_COMMIT();

        const uint32_t sA = smem_base + (c % STAGES) * STAGE_BYTES;
        const uint32_t sB = sA + A_STAGE;

        #pragma unroll
        for (int ks = 0; ks < 2; ks++) {
            const uint32_t ko = ks * 32;
            uint32_t a[4][4], b[8][2];
            #pragma unroll
            for (int mi = 0; mi < 4; mi++)
                LDSM_X4(a[mi][0], a[mi][1], a[mi][2], a[mi][3],
                        sA + aOff + mi * 16 * ROW_PITCH + ko);
            #pragma unroll
            for (int np = 0; np < 4; np++)
                LDSM_X4(b[2 * np][0], b[2 * np][1], b[2 * np + 1][0], b[2 * np + 1][1],
                        sB + bOff + np * 16 * ROW_PITCH + ko);
            #pragma unroll
            for (int mi = 0; mi < 4; mi++)
                #pragma unroll
                for (int ni = 0; ni < 8; ni++)
                    imma_16832(acc[mi][ni], a[mi][0], a[mi][1], a[mi][2], a[mi][3],
                               b[ni][0], b[ni][1]);
        }
    }

    // -------- epilogue: int32 -> float, + bias --------
    const int gm0 = blockIdx.y * BM + wm * 64;
    const int gn0 = blockIdx.x * BN + wn * 64;
    #pragma unroll
    for (int ni = 0; ni < 8; ni++) {
        const int col = gn0 + ni * 8 + tg * 2;
        const float2 bb = *reinterpret_cast<const float2*>(bias + col);
        #pragma unroll
        for (int mi = 0; mi < 4; mi++) {
            const int row0 = gm0 + mi * 16 + g;
            float2 o0, o1;
            o0.x = __int2float_rn(acc[mi][ni][0]) + bb.x;
            o0.y = __int2float_rn(acc[mi][ni][1]) + bb.y;
            o1.x = __int2float_rn(acc[mi][ni][2]) + bb.x;
            o1.y = __int2float_rn(acc[mi][ni][3]) + bb.y;
            *reinterpret_cast<float2*>(out + (size_t)row0 * DOUT + col)       = o0;
            *reinterpret_cast<float2*>(out + (size_t)(row0 + 8) * DOUT + col) = o1;
        }
    }
}

// ---------------- launch ----------------
extern "C" void kernel_launch(void* const* d_in, const int* in_sizes, int n_in,
                              void* d_out, int out_size) {
    const float* x    = (const float*)d_in[0];   // [4,2048,2048] fp32
    const float* w    = (const float*)d_in[1];   // [2048,2048] fp32
    const float* xs   = (const float*)d_in[2];   // scalar fp32
    const float* bias = (const float*)d_in[3];   // [2048] fp32
    float* out = (float*)d_out;

    quant_x_kernel<<<(MTOT * DIN / 16 + 255) / 256, 256>>>(x, xs);
    conv_wt_kernel<<<dim3(DOUT / 32, DIN / 128), dim3(32, 8)>>>(w);

    static int configured = 0;
    if (!configured) {
        cudaFuncSetAttribute(gemm_kernel, cudaFuncAttributeMaxDynamicSharedMemorySize, SMEM_TOTAL);
        configured = 1;
    }
    gemm_kernel<<<dim3(DOUT / BN, MTOT / BM), NTHREADS, SMEM_TOTAL>>>(bias, out);
}

// round 4
// speedup vs baseline: 1.2393x; 1.2393x over previous
#include <cuda_runtime.h>
#include <cuda_bf16.h>
#include <cstdint>

#define DIN   2048
#define DOUT  2048
#define MTOT  8192

// ---------------- scratch (static device globals; no allocation) ----------------
__device__ int8_t g_xq[(size_t)MTOT * DIN];   // quantized activations, [M][K] int8
__device__ int8_t g_wt[(size_t)DOUT * DIN];   // W transposed+quantized, [N][K] int8

// ---------------- helpers ----------------
__device__ __forceinline__ uint32_t smem_u32(const void* p) {
    uint32_t a;
    asm("{ .reg .u64 t; cvta.to.shared.u64 t, %1; cvt.u32.u64 %0, t; }" : "=r"(a) : "l"(p));
    return a;
}

#define CP_ASYNC16(dst, src) \
    asm volatile("cp.async.cg.shared.global [%0], [%1], 16;" :: "r"(dst), "l"(src) : "memory")
#define CP_ASYNC_COMMIT() asm volatile("cp.async.commit_group;" ::: "memory")
#define CP_ASYNC_WAIT(n)  asm volatile("cp.async.wait_group %0;" :: "n"(n) : "memory")

#define LDSM_X4(r0, r1, r2, r3, addr) \
    asm volatile("ldmatrix.sync.aligned.m8n8.x4.shared.b16 {%0,%1,%2,%3}, [%4];" \
                 : "=r"(r0), "=r"(r1), "=r"(r2), "=r"(r3) : "r"(addr))

__device__ __forceinline__ void imma_16832(int* c, uint32_t a0, uint32_t a1, uint32_t a2, uint32_t a3,
                                           uint32_t b0, uint32_t b1) {
    asm volatile(
        "mma.sync.aligned.m16n8k32.row.col.s32.s8.s8.s32 "
        "{%0,%1,%2,%3}, {%4,%5,%6,%7}, {%8,%9}, {%0,%1,%2,%3};"
        : "+r"(c[0]), "+r"(c[1]), "+r"(c[2]), "+r"(c[3])
        : "r"(a0), "r"(a1), "r"(a2), "r"(a3), "r"(b0), "r"(b1));
}

// ---------------- fused pre-pass: quantize x AND transpose+quantize W ----------------
// blocks [0, 4096): quantize x (each thread 16 elems)
// blocks [4096, 5120): transpose W 32n x 128k tiles
#define QX_BLOCKS 4096
__global__ void prep_kernel(const float* __restrict__ x, const float* __restrict__ w,
                            const float* __restrict__ scale_p) {
    if (blockIdx.x < QX_BLOCKS) {
        const float inv_s = 1.0f / fmaxf(scale_p[0], 1e-8f);
        const int i = blockIdx.x * blockDim.x + threadIdx.x;   // 0 .. M*K/16-1
        const float4* xin = reinterpret_cast<const float4*>(x) + (size_t)i * 4;
        int packed[4];
        #pragma unroll
        for (int j = 0; j < 4; j++) {
            float4 v = xin[j];
            int q0 = __float2int_rn(fminf(fmaxf(v.x * inv_s, -127.f), 127.f));
            int q1 = __float2int_rn(fminf(fmaxf(v.y * inv_s, -127.f), 127.f));
            int q2 = __float2int_rn(fminf(fmaxf(v.z * inv_s, -127.f), 127.f));
            int q3 = __float2int_rn(fminf(fmaxf(v.w * inv_s, -127.f), 127.f));
            packed[j] = (q0 & 0xFF) | ((q1 & 0xFF) << 8) | ((q2 & 0xFF) << 16) | (q3 << 24);
        }
        reinterpret_cast<int4*>(g_xq)[i] = make_int4(packed[0], packed[1], packed[2], packed[3]);
    } else {
        __shared__ float t[128][33];     // [k][n]
        const int bid = blockIdx.x - QX_BLOCKS;        // 0..1023
        const int bx = (bid & 63) * 32;                // n tile
        const int by = (bid >> 6) * 128;               // k tile
        const int tx = threadIdx.x & 31;
        const int ty = threadIdx.x >> 5;               // 0..7
        #pragma unroll
        for (int i = ty; i < 128; i += 8)
            t[i][tx] = w[(size_t)(by + i) * DOUT + bx + tx];   // coalesced reads
        __syncthreads();
        #pragma unroll
        for (int r = 0; r < 4; r++) {
            const int n = ty + r * 8;
            char4 c;
            c.x = (char)__float2int_rn(t[tx * 4 + 0][n]);
            c.y = (char)__float2int_rn(t[tx * 4 + 1][n]);
            c.z = (char)__float2int_rn(t[tx * 4 + 2][n]);
            c.w = (char)__float2int_rn(t[tx * 4 + 3][n]);
            *reinterpret_cast<char4*>(&g_wt[(size_t)(bx + n) * DIN + by + tx * 4]) = c;
        }
    }
}

// ---------------- GEMM: out[M,N] = xq @ wt^T + bias (int8 IMMA, 128x64x64, occ 3) ----------------
#define BM 128
#define BN 64
#define BK 64
#define STAGES 4
#define NTHREADS 256
#define NCHUNKS (DIN / BK)        // 32

#define ROW_PITCH 80                         // 64B data + 16B pad: LDSM phases conflict-free
#define A_STAGE   (BM * ROW_PITCH)           // 10240
#define B_STAGE   (BN * ROW_PITCH)           // 5120
#define STAGE_BYTES (A_STAGE + B_STAGE)      // 15360
#define SMEM_TOTAL (STAGES * STAGE_BYTES)    // 61440

__global__ void __launch_bounds__(NTHREADS, 3) gemm_kernel(const float* __restrict__ bias,
                                                           float* __restrict__ out) {
    extern __shared__ __align__(128) char smem[];
    const uint32_t smem_base = smem_u32(smem);

    const int tid  = threadIdx.x;
    const int wid  = tid >> 5;
    const int lane = tid & 31;
    const int wm   = wid >> 1;        // 0..3 : 32-row M block
    const int wn   = wid & 1;         // 0..1 : 32-col N block
    const int g    = lane >> 2;
    const int tg   = lane & 3;

    const int8_t* Arow = g_xq + (size_t)blockIdx.y * BM * DIN;
    const int8_t* Brow = g_wt + (size_t)blockIdx.x * BN * DIN;

    // -------- async stage loader: 192 rows x 64B = 768 16B-vectors / 256 thr = 3 each --------
    auto load_stage = [&](int stage, int chunk) {
        const int k0 = chunk * BK;
        const uint32_t base = smem_base + stage * STAGE_BYTES;
        #pragma unroll
        for (int j = 0; j < 3; j++) {
            const int v   = tid + j * 256;
            const int r   = v >> 2;
            const int c16 = (v & 3) * 16;
            if (r < BM) {
                CP_ASYNC16(base + r * ROW_PITCH + c16, Arow + (size_t)r * DIN + k0 + c16);
            } else {
                const int r2 = r - BM;
                CP_ASYNC16(base + A_STAGE + r2 * ROW_PITCH + c16, Brow + (size_t)r2 * DIN + k0 + c16);
            }
        }
    };

    int acc[2][4][4];
    #pragma unroll
    for (int mi = 0; mi < 2; mi++)
        #pragma unroll
        for (int ni = 0; ni < 4; ni++)
            #pragma unroll
            for (int q = 0; q < 4; q++) acc[mi][ni][q] = 0;

    #pragma unroll
    for (int s = 0; s < STAGES - 1; s++) {
        load_stage(s, s);
        CP_ASYNC_COMMIT();
    }

    // ldmatrix per-lane base addresses (mapping validated in R3, rel_err = 0)
    const uint32_t aOff = (uint32_t)(wm * 32 + (lane & 15)) * ROW_PITCH + ((lane >> 4) * 16);
    const uint32_t bOff = (uint32_t)(wn * 32 + (lane & 7) + ((lane >> 4) << 3)) * ROW_PITCH
                          + ((lane & 8) ? 16u : 0u);

    for (int c = 0; c < NCHUNKS; c++) {
        CP_ASYNC_WAIT(STAGES - 2);
        __syncthreads();

        if (c + STAGES - 1 < NCHUNKS) load_stage((c + STAGES - 1) % STAGES, c + STAGES - 1);
        CP_ASYNC_COMMIT();

        const uint32_t sA = smem_base + (c % STAGES) * STAGE_BYTES;
        const uint32_t sB = sA + A_STAGE;

        #pragma unroll
        for (int ks = 0; ks < 2; ks++) {
            const uint32_t ko = ks * 32;
            uint32_t a[2][4], b[4][2];
            #pragma unroll
            for (int mi = 0; mi < 2; mi++)
                LDSM_X4(a[mi][0], a[mi][1], a[mi][2], a[mi][3],
                        sA + aOff + mi * 16 * ROW_PITCH + ko);
            #pragma unroll
            for (int np = 0; np < 2; np++)
                LDSM_X4(b[2 * np][0], b[2 * np][1], b[2 * np + 1][0], b[2 * np + 1][1],
                        sB + bOff + np * 16 * ROW_PITCH + ko);
            #pragma unroll
            for (int mi = 0; mi < 2; mi++)
                #pragma unroll
                for (int ni = 0; ni < 4; ni++)
                    imma_16832(acc[mi][ni], a[mi][0], a[mi][1], a[mi][2], a[mi][3],
                               b[ni][0], b[ni][1]);
        }
    }

    // -------- epilogue: int32 -> float, + bias --------
    const int gm0 = blockIdx.y * BM + wm * 32;
    const int gn0 = blockIdx.x * BN + wn * 32;
    #pragma unroll
    for (int ni = 0; ni < 4; ni++) {
        const int col = gn0 + ni * 8 + tg * 2;
        const float2 bb = *reinterpret_cast<const float2*>(bias + col);
        #pragma unroll
        for (int mi = 0; mi < 2; mi++) {
            const int row0 = gm0 + mi * 16 + g;
            float2 o0, o1;
            o0.x = __int2float_rn(acc[mi][ni][0]) + bb.x;
            o0.y = __int2float_rn(acc[mi][ni][1]) + bb.y;
            o1.x = __int2float_rn(acc[mi][ni][2]) + bb.x;
            o1.y = __int2float_rn(acc[mi][ni][3]) + bb.y;
            *reinterpret_cast<float2*>(out + (size_t)row0 * DOUT + col)       = o0;
            *reinterpret_cast<float2*>(out + (size_t)(row0 + 8) * DOUT + col) = o1;
        }
    }
}

// ---------------- launch ----------------
extern "C" void kernel_launch(void* const* d_in, const int* in_sizes, int n_in,
                              void* d_out, int out_size) {
    const float* x    = (const float*)d_in[0];   // [4,2048,2048] fp32
    const float* w    = (const float*)d_in[1];   // [2048,2048] fp32
    const float* xs   = (const float*)d_in[2];   // scalar fp32
    const float* bias = (const float*)d_in[3];   // [2048] fp32
    float* out = (float*)d_out;

    prep_kernel<<<QX_BLOCKS + 1024, 256>>>(x, w, xs);

    static int configured = 0;
    if (!configured) {
        cudaFuncSetAttribute(gemm_kernel, cudaFuncAttributeMaxDynamicSharedMemorySize, SMEM_TOTAL);
        configured = 1;
    }
    gemm_kernel<<<dim3(DOUT / BN, MTOT / BM), NTHREADS, SMEM_TOTAL>>>(bias, out);
}

// round 5
// speedup vs baseline: 1.3112x; 1.0580x over previous
#include <cuda_runtime.h>
#include <cuda_bf16.h>
#include <cstdint>

#define DIN   2048
#define DOUT  2048
#define MTOT  8192

// N-split: int8 IMMA covers cols [0, NSPLIT), bf16 HMMA covers [NSPLIT, DOUT)
#define NSPLIT 1536

// ---------------- scratch (static device globals; no allocation) ----------------
__device__ int8_t         g_xq [(size_t)MTOT * DIN];   // x quantized, [M][K] int8
__device__ __nv_bfloat16  g_xbf[(size_t)MTOT * DIN];   // x quantized, [M][K] bf16
__device__ int8_t         g_wt [(size_t)DOUT * DIN];   // W^T quantized-int, [N][K] int8
__device__ __nv_bfloat16  g_wbf[(size_t)DOUT * DIN];   // W^T as bf16,      [N][K] bf16

// ---------------- helpers ----------------
__device__ __forceinline__ uint32_t smem_u32(const void* p) {
    uint32_t a;
    asm("{ .reg .u64 t; cvta.to.shared.u64 t, %1; cvt.u32.u64 %0, t; }" : "=r"(a) : "l"(p));
    return a;
}

#define CP_ASYNC16(dst, src) \
    asm volatile("cp.async.cg.shared.global [%0], [%1], 16;" :: "r"(dst), "l"(src) : "memory")
#define CP_ASYNC_COMMIT() asm volatile("cp.async.commit_group;" ::: "memory")
#define CP_ASYNC_WAIT(n)  asm volatile("cp.async.wait_group %0;" :: "n"(n) : "memory")

#define LDSM_X4(r0, r1, r2, r3, addr) \
    asm volatile("ldmatrix.sync.aligned.m8n8.x4.shared.b16 {%0,%1,%2,%3}, [%4];" \
                 : "=r"(r0), "=r"(r1), "=r"(r2), "=r"(r3) : "r"(addr))

__device__ __forceinline__ void imma_16832(int* c, uint32_t a0, uint32_t a1, uint32_t a2, uint32_t a3,
                                           uint32_t b0, uint32_t b1) {
    asm volatile(
        "mma.sync.aligned.m16n8k32.row.col.s32.s8.s8.s32 "
        "{%0,%1,%2,%3}, {%4,%5,%6,%7}, {%8,%9}, {%0,%1,%2,%3};"
        : "+r"(c[0]), "+r"(c[1]), "+r"(c[2]), "+r"(c[3])
        : "r"(a0), "r"(a1), "r"(a2), "r"(a3), "r"(b0), "r"(b1));
}

__device__ __forceinline__ void hmma_16816(float* c, uint32_t a0, uint32_t a1, uint32_t a2, uint32_t a3,
                                           uint32_t b0, uint32_t b1) {
    asm volatile(
        "mma.sync.aligned.m16n8k16.row.col.f32.bf16.bf16.f32 "
        "{%0,%1,%2,%3}, {%4,%5,%6,%7}, {%8,%9}, {%0,%1,%2,%3};"
        : "+f"(c[0]), "+f"(c[1]), "+f"(c[2]), "+f"(c[3])
        : "r"(a0), "r"(a1), "r"(a2), "r"(a3), "r"(b0), "r"(b1));
}

// ---------------- fused pre-pass: quantize x (int8 + bf16) AND transpose W (int8 + bf16) ----------------
#define QX_BLOCKS 4096
__global__ void prep_kernel(const float* __restrict__ x, const float* __restrict__ w,
                            const float* __restrict__ scale_p) {
    if (blockIdx.x < QX_BLOCKS) {
        const float inv_s = 1.0f / fmaxf(scale_p[0], 1e-8f);
        const int i = blockIdx.x * blockDim.x + threadIdx.x;   // 0 .. M*K/16-1
        const float4* xin = reinterpret_cast<const float4*>(x) + (size_t)i * 4;
        int packed[4];
        uint32_t bfp[8];
        #pragma unroll
        for (int j = 0; j < 4; j++) {
            float4 v = xin[j];
            float f0 = fminf(fmaxf(rintf(v.x * inv_s), -127.f), 127.f);
            float f1 = fminf(fmaxf(rintf(v.y * inv_s), -127.f), 127.f);
            float f2 = fminf(fmaxf(rintf(v.z * inv_s), -127.f), 127.f);
            float f3 = fminf(fmaxf(rintf(v.w * inv_s), -127.f), 127.f);
            int q0 = (int)f0, q1 = (int)f1, q2 = (int)f2, q3 = (int)f3;
            packed[j] = (q0 & 0xFF) | ((q1 & 0xFF) << 8) | ((q2 & 0xFF) << 16) | (q3 << 24);
            __nv_bfloat162 p0 = __floats2bfloat162_rn(f0, f1);
            __nv_bfloat162 p1 = __floats2bfloat162_rn(f2, f3);
            bfp[2 * j]     = *reinterpret_cast<uint32_t*>(&p0);
            bfp[2 * j + 1] = *reinterpret_cast<uint32_t*>(&p1);
        }
        reinterpret_cast<int4*>(g_xq)[i] = make_int4(packed[0], packed[1], packed[2], packed[3]);
        uint4* bo = reinterpret_cast<uint4*>(g_xbf) + (size_t)i * 2;
        bo[0] = make_uint4(bfp[0], bfp[1], bfp[2], bfp[3]);
        bo[1] = make_uint4(bfp[4], bfp[5], bfp[6], bfp[7]);
    } else {
        __shared__ float t[128][33];     // [k][n]
        const int bid = blockIdx.x - QX_BLOCKS;        // 0..1023
        const int bx = (bid & 63) * 32;                // n tile
        const int by = (bid >> 6) * 128;               // k tile
        const int tx = threadIdx.x & 31;
        const int ty = threadIdx.x >> 5;               // 0..7
        #pragma unroll
        for (int i = ty; i < 128; i += 8)
            t[i][tx] = w[(size_t)(by + i) * DOUT + bx + tx];   // coalesced reads
        __syncthreads();
        #pragma unroll
        for (int r = 0; r < 4; r++) {
            const int n = ty + r * 8;
            float f0 = t[tx * 4 + 0][n], f1 = t[tx * 4 + 1][n];
            float f2 = t[tx * 4 + 2][n], f3 = t[tx * 4 + 3][n];
            char4 c;
            c.x = (char)__float2int_rn(f0); c.y = (char)__float2int_rn(f1);
            c.z = (char)__float2int_rn(f2); c.w = (char)__float2int_rn(f3);
            *reinterpret_cast<char4*>(&g_wt[(size_t)(bx + n) * DIN + by + tx * 4]) = c;
            __nv_bfloat162 p0 = __floats2bfloat162_rn(f0, f1);
            __nv_bfloat162 p1 = __floats2bfloat162_rn(f2, f3);
            uint2 bo;
            bo.x = *reinterpret_cast<uint32_t*>(&p0);
            bo.y = *reinterpret_cast<uint32_t*>(&p1);
            *reinterpret_cast<uint2*>(&g_wbf[(size_t)(bx + n) * DIN + by + tx * 4]) = bo;
        }
    }
}

// ---------------- common tile geometry (both GEMMs: 64B K-rows, pitch 80) ----------------
#define BM 128
#define BN 64
#define STAGES 4
#define NTHREADS 256
#define ROW_PITCH 80
#define A_STAGE   (BM * ROW_PITCH)           // 10240
#define B_STAGE   (BN * ROW_PITCH)           // 5120
#define STAGE_BYTES (A_STAGE + B_STAGE)      // 15360
#define SMEM_TOTAL (STAGES * STAGE_BYTES)    // 61440

// ---------------- GEMM 1: int8 IMMA, cols [0, NSPLIT) ----------------
#define BK8 64
#define NCHUNKS8 (DIN / BK8)        // 32

__global__ void __launch_bounds__(NTHREADS, 3) gemm_i8_kernel(const float* __restrict__ bias,
                                                              float* __restrict__ out) {
    extern __shared__ __align__(128) char smem[];
    const uint32_t smem_base = smem_u32(smem);
    const int tid  = threadIdx.x;
    const int wid  = tid >> 5;
    const int lane = tid & 31;
    const int wm   = wid >> 1;
    const int wn   = wid & 1;
    const int g    = lane >> 2;
    const int tg   = lane & 3;

    const int8_t* Arow = g_xq + (size_t)blockIdx.y * BM * DIN;
    const int8_t* Brow = g_wt + (size_t)blockIdx.x * BN * DIN;

    auto load_stage = [&](int stage, int chunk) {
        const int k0 = chunk * BK8;
        const uint32_t base = smem_base + stage * STAGE_BYTES;
        #pragma unroll
        for (int j = 0; j < 3; j++) {
            const int v   = tid + j * 256;
            const int r   = v >> 2;
            const int c16 = (v & 3) * 16;
            if (r < BM) {
                CP_ASYNC16(base + r * ROW_PITCH + c16, Arow + (size_t)r * DIN + k0 + c16);
            } else {
                const int r2 = r - BM;
                CP_ASYNC16(base + A_STAGE + r2 * ROW_PITCH + c16, Brow + (size_t)r2 * DIN + k0 + c16);
            }
        }
    };

    int acc[2][4][4];
    #pragma unroll
    for (int mi = 0; mi < 2; mi++)
        #pragma unroll
        for (int ni = 0; ni < 4; ni++)
            #pragma unroll
            for (int q = 0; q < 4; q++) acc[mi][ni][q] = 0;

    #pragma unroll
    for (int s = 0; s < STAGES - 1; s++) { load_stage(s, s); CP_ASYNC_COMMIT(); }

    const uint32_t aOff = (uint32_t)(wm * 32 + (lane & 15)) * ROW_PITCH + ((lane >> 4) * 16);
    const uint32_t bOff = (uint32_t)(wn * 32 + (lane & 7) + ((lane >> 4) << 3)) * ROW_PITCH
                          + ((lane & 8) ? 16u : 0u);

    for (int c = 0; c < NCHUNKS8; c++) {
        CP_ASYNC_WAIT(STAGES - 2);
        __syncthreads();
        if (c + STAGES - 1 < NCHUNKS8) load_stage((c + STAGES - 1) % STAGES, c + STAGES - 1);
        CP_ASYNC_COMMIT();

        const uint32_t sA = smem_base + (c % STAGES) * STAGE_BYTES;
        const uint32_t sB = sA + A_STAGE;
        #pragma unroll
        for (int ks = 0; ks < 2; ks++) {
            const uint32_t ko = ks * 32;
            uint32_t a[2][4], b[4][2];
            #pragma unroll
            for (int mi = 0; mi < 2; mi++)
                LDSM_X4(a[mi][0], a[mi][1], a[mi][2], a[mi][3], sA + aOff + mi * 16 * ROW_PITCH + ko);
            #pragma unroll
            for (int np = 0; np < 2; np++)
                LDSM_X4(b[2 * np][0], b[2 * np][1], b[2 * np + 1][0], b[2 * np + 1][1],
                        sB + bOff + np * 16 * ROW_PITCH + ko);
            #pragma unroll
            for (int mi = 0; mi < 2; mi++)
                #pragma unroll
                for (int ni = 0; ni < 4; ni++)
                    imma_16832(acc[mi][ni], a[mi][0], a[mi][1], a[mi][2], a[mi][3], b[ni][0], b[ni][1]);
        }
    }

    const int gm0 = blockIdx.y * BM + wm * 32;
    const int gn0 = blockIdx.x * BN + wn * 32;
    #pragma unroll
    for (int ni = 0; ni < 4; ni++) {
        const int col = gn0 + ni * 8 + tg * 2;
        const float2 bb = *reinterpret_cast<const float2*>(bias + col);
        #pragma unroll
        for (int mi = 0; mi < 2; mi++) {
            const int row0 = gm0 + mi * 16 + g;
            float2 o0, o1;
            o0.x = __int2float_rn(acc[mi][ni][0]) + bb.x;
            o0.y = __int2float_rn(acc[mi][ni][1]) + bb.y;
            o1.x = __int2float_rn(acc[mi][ni][2]) + bb.x;
            o1.y = __int2float_rn(acc[mi][ni][3]) + bb.y;
            *reinterpret_cast<float2*>(out + (size_t)row0 * DOUT + col)       = o0;
            *reinterpret_cast<float2*>(out + (size_t)(row0 + 8) * DOUT + col) = o1;
        }
    }
}

// ---------------- GEMM 2: bf16 HMMA, cols [NSPLIT, DOUT) ----------------
#define BK16 32
#define NCHUNKS16 (DIN / BK16)      // 64

__global__ void __launch_bounds__(NTHREADS, 3) gemm_bf16_kernel(const float* __restrict__ bias,
                                                                float* __restrict__ out) {
    extern __shared__ __align__(128) char smem[];
    const uint32_t smem_base = smem_u32(smem);
    const int tid  = threadIdx.x;
    const int wid  = tid >> 5;
    const int lane = tid & 31;
    const int wm   = wid >> 1;
    const int wn   = wid & 1;
    const int g    = lane >> 2;
    const int tg   = lane & 3;

    const __nv_bfloat16* Arow = g_xbf + (size_t)blockIdx.y * BM * DIN;
    const __nv_bfloat16* Brow = g_wbf + (size_t)(NSPLIT + blockIdx.x * BN) * DIN;

    auto load_stage = [&](int stage, int chunk) {
        const int k0 = chunk * BK16;            // in bf16 elements (64 bytes)
        const uint32_t base = smem_base + stage * STAGE_BYTES;
        #pragma unroll
        for (int j = 0; j < 3; j++) {
            const int v   = tid + j * 256;
            const int r   = v >> 2;
            const int c16 = (v & 3) * 16;       // byte offset within 64B row
            if (r < BM) {
                CP_ASYNC16(base + r * ROW_PITCH + c16,
                           reinterpret_cast<const char*>(Arow + (size_t)r * DIN + k0) + c16);
            } else {
                const int r2 = r - BM;
                CP_ASYNC16(base + A_STAGE + r2 * ROW_PITCH + c16,
                           reinterpret_cast<const char*>(Brow + (size_t)r2 * DIN + k0) + c16);
            }
        }
    };

    float acc[2][4][4];
    #pragma unroll
    for (int mi = 0; mi < 2; mi++)
        #pragma unroll
        for (int ni = 0; ni < 4; ni++)
            #pragma unroll
            for (int q = 0; q < 4; q++) acc[mi][ni][q] = 0.f;

    #pragma unroll
    for (int s = 0; s < STAGES - 1; s++) { load_stage(s, s); CP_ASYNC_COMMIT(); }

    // A x4: rows (lane&15) of 16-row block, +16B for k8-15 half (8 bf16)
    const uint32_t aOff = (uint32_t)(wm * 32 + (lane & 15)) * ROW_PITCH + ((lane >> 4) * 16);
    // B x4: n rows (lane&7) + 8*(lane>>4), +16B for k8-15 half (lanes 8-15 / 24-31)
    const uint32_t bOff = (uint32_t)(wn * 32 + (lane & 7) + ((lane >> 4) << 3)) * ROW_PITCH
                          + ((lane & 8) ? 16u : 0u);

    for (int c = 0; c < NCHUNKS16; c++) {
        CP_ASYNC_WAIT(STAGES - 2);
        __syncthreads();
        if (c + STAGES - 1 < NCHUNKS16) load_stage((c + STAGES - 1) % STAGES, c + STAGES - 1);
        CP_ASYNC_COMMIT();

        const uint32_t sA = smem_base + (c % STAGES) * STAGE_BYTES;
        const uint32_t sB = sA + A_STAGE;
        #pragma unroll
        for (int ks = 0; ks < 2; ks++) {        // k16 step = 32 bytes
            const uint32_t ko = ks * 32;
            uint32_t a[2][4], b[4][2];
            #pragma unroll
            for (int mi = 0; mi < 2; mi++)
                LDSM_X4(a[mi][0], a[mi][1], a[mi][2], a[mi][3], sA + aOff + mi * 16 * ROW_PITCH + ko);
            #pragma unroll
            for (int np = 0; np < 2; np++)
                LDSM_X4(b[2 * np][0], b[2 * np][1], b[2 * np + 1][0], b[2 * np + 1][1],
                        sB + bOff + np * 16 * ROW_PITCH + ko);
            #pragma unroll
            for (int mi = 0; mi < 2; mi++)
                #pragma unroll
                for (int ni = 0; ni < 4; ni++)
                    hmma_16816(acc[mi][ni], a[mi][0], a[mi][1], a[mi][2], a[mi][3], b[ni][0], b[ni][1]);
        }
    }

    const int gm0 = blockIdx.y * BM + wm * 32;
    const int gn0 = NSPLIT + blockIdx.x * BN + wn * 32;
    #pragma unroll
    for (int ni = 0; ni < 4; ni++) {
        const int col = gn0 + ni * 8 + tg * 2;
        const float2 bb = *reinterpret_cast<const float2*>(bias + col);
        #pragma unroll
        for (int mi = 0; mi < 2; mi++) {
            const int row0 = gm0 + mi * 16 + g;
            float2 o0, o1;
            o0.x = acc[mi][ni][0] + bb.x;
            o0.y = acc[mi][ni][1] + bb.y;
            o1.x = acc[mi][ni][2] + bb.x;
            o1.y = acc[mi][ni][3] + bb.y;
            *reinterpret_cast<float2*>(out + (size_t)row0 * DOUT + col)       = o0;
            *reinterpret_cast<float2*>(out + (size_t)(row0 + 8) * DOUT + col) = o1;
        }
    }
}

// ---------------- launch ----------------
extern "C" void kernel_launch(void* const* d_in, const int* in_sizes, int n_in,
                              void* d_out, int out_size) {
    const float* x    = (const float*)d_in[0];   // [4,2048,2048] fp32
    const float* w    = (const float*)d_in[1];   // [2048,2048] fp32
    const float* xs   = (const float*)d_in[2];   // scalar fp32
    const float* bias = (const float*)d_in[3];   // [2048] fp32
    float* out = (float*)d_out;

    prep_kernel<<<QX_BLOCKS + 1024, 256>>>(x, w, xs);

    static int configured = 0;
    if (!configured) {
        cudaFuncSetAttribute(gemm_i8_kernel,   cudaFuncAttributeMaxDynamicSharedMemorySize, SMEM_TOTAL);
        cudaFuncSetAttribute(gemm_bf16_kernel, cudaFuncAttributeMaxDynamicSharedMemorySize, SMEM_TOTAL);
        configured = 1;
    }
    gemm_i8_kernel<<<dim3(NSPLIT / BN, MTOT / BM), NTHREADS, SMEM_TOTAL>>>(bias, out);
    gemm_bf16_kernel<<<dim3((DOUT - NSPLIT) / BN, MTOT / BM), NTHREADS, SMEM_TOTAL>>>(bias, out);
}

// round 6
// speedup vs baseline: 2.4267x; 1.8508x over previous
#include <cuda_runtime.h>
#include <cuda_bf16.h>
#include <cstdint>

#define DIN   2048
#define DOUT  2048
#define MTOT  8192

// ---------------- scratch (static device globals; no allocation) ----------------
__device__ __nv_bfloat16  g_xbf[(size_t)MTOT * DIN];   // x quantized, [M][K] bf16
__device__ __nv_bfloat16  g_wbf[(size_t)DOUT * DIN];   // W^T as bf16, [N][K] bf16

// ---------------- helpers ----------------
__device__ __forceinline__ uint32_t smem_u32(const void* p) {
    uint32_t a;
    asm("{ .reg .u64 t; cvta.to.shared.u64 t, %1; cvt.u32.u64 %0, t; }" : "=r"(a) : "l"(p));
    return a;
}

#define CP_ASYNC16(dst, src) \
    asm volatile("cp.async.cg.shared.global [%0], [%1], 16;" :: "r"(dst), "l"(src) : "memory")
#define CP_ASYNC_COMMIT() asm volatile("cp.async.commit_group;" ::: "memory")
#define CP_ASYNC_WAIT(n)  asm volatile("cp.async.wait_group %0;" :: "n"(n) : "memory")

#define LDSM_X4(r0, r1, r2, r3, addr) \
    asm volatile("ldmatrix.sync.aligned.m8n8.x4.shared.b16 {%0,%1,%2,%3}, [%4];" \
                 : "=r"(r0), "=r"(r1), "=r"(r2), "=r"(r3) : "r"(addr))

__device__ __forceinline__ void hmma_16816(float* c, uint32_t a0, uint32_t a1, uint32_t a2, uint32_t a3,
                                           uint32_t b0, uint32_t b1) {
    asm volatile(
        "mma.sync.aligned.m16n8k16.row.col.f32.bf16.bf16.f32 "
        "{%0,%1,%2,%3}, {%4,%5,%6,%7}, {%8,%9}, {%0,%1,%2,%3};"
        : "+f"(c[0]), "+f"(c[1]), "+f"(c[2]), "+f"(c[3])
        : "r"(a0), "r"(a1), "r"(a2), "r"(a3), "r"(b0), "r"(b1));
}

// ---------------- fused pre-pass: quantize x -> bf16 AND transpose W -> bf16 ----------------
#define QX_BLOCKS 4096
__global__ void prep_kernel(const float* __restrict__ x, const float* __restrict__ w,
                            const float* __restrict__ scale_p) {
    if (blockIdx.x < QX_BLOCKS) {
        const float inv_s = 1.0f / fmaxf(scale_p[0], 1e-8f);
        const int i = blockIdx.x * blockDim.x + threadIdx.x;   // 0 .. M*K/16-1
        const float4* xin = reinterpret_cast<const float4*>(x) + (size_t)i * 4;
        uint32_t bfp[8];
        #pragma unroll
        for (int j = 0; j < 4; j++) {
            float4 v = xin[j];
            float f0 = fminf(fmaxf(rintf(v.x * inv_s), -127.f), 127.f);
            float f1 = fminf(fmaxf(rintf(v.y * inv_s), -127.f), 127.f);
            float f2 = fminf(fmaxf(rintf(v.z * inv_s), -127.f), 127.f);
            float f3 = fminf(fmaxf(rintf(v.w * inv_s), -127.f), 127.f);
            __nv_bfloat162 p0 = __floats2bfloat162_rn(f0, f1);
            __nv_bfloat162 p1 = __floats2bfloat162_rn(f2, f3);
            bfp[2 * j]     = *reinterpret_cast<uint32_t*>(&p0);
            bfp[2 * j + 1] = *reinterpret_cast<uint32_t*>(&p1);
        }
        uint4* bo = reinterpret_cast<uint4*>(g_xbf) + (size_t)i * 2;
        bo[0] = make_uint4(bfp[0], bfp[1], bfp[2], bfp[3]);
        bo[1] = make_uint4(bfp[4], bfp[5], bfp[6], bfp[7]);
    } else {
        __shared__ float t[128][33];     // [k][n]
        const int bid = blockIdx.x - QX_BLOCKS;        // 0..1023
        const int bx = (bid & 63) * 32;                // n tile
        const int by = (bid >> 6) * 128;               // k tile
        const int tx = threadIdx.x & 31;
        const int ty = threadIdx.x >> 5;               // 0..7
        #pragma unroll
        for (int i = ty; i < 128; i += 8)
            t[i][tx] = w[(size_t)(by + i) * DOUT + bx + tx];   // coalesced reads
        __syncthreads();
        #pragma unroll
        for (int r = 0; r < 4; r++) {
            const int n = ty + r * 8;
            __nv_bfloat162 p0 = __floats2bfloat162_rn(t[tx * 4 + 0][n], t[tx * 4 + 1][n]);
            __nv_bfloat162 p1 = __floats2bfloat162_rn(t[tx * 4 + 2][n], t[tx * 4 + 3][n]);
            uint2 bo;
            bo.x = *reinterpret_cast<uint32_t*>(&p0);
            bo.y = *reinterpret_cast<uint32_t*>(&p1);
            *reinterpret_cast<uint2*>(&g_wbf[(size_t)(bx + n) * DIN + by + tx * 4]) = bo;
        }
    }
}

// ---------------- GEMM: out[M,N] = xbf @ wbf^T + bias (bf16 HMMA, 128x64x32, occ 3) ----------------
#define BM 128
#define BN 64
#define BK 32                                // bf16 elements = 64 bytes per row-chunk
#define STAGES 4
#define NTHREADS 256
#define NCHUNKS (DIN / BK)                   // 64

#define ROW_PITCH 80                         // 64B data + 16B pad: LDSM phases conflict-free
#define A_STAGE   (BM * ROW_PITCH)           // 10240
#define B_STAGE   (BN * ROW_PITCH)           // 5120
#define STAGE_BYTES (A_STAGE + B_STAGE)      // 15360
#define SMEM_TOTAL (STAGES * STAGE_BYTES)    // 61440

__global__ void __launch_bounds__(NTHREADS, 3) gemm_bf16_kernel(const float* __restrict__ bias,
                                                                float* __restrict__ out) {
    extern __shared__ __align__(128) char smem[];
    const uint32_t smem_base = smem_u32(smem);
    const int tid  = threadIdx.x;
    const int wid  = tid >> 5;
    const int lane = tid & 31;
    const int wm   = wid >> 1;        // 0..3 : 32-row M block
    const int wn   = wid & 1;         // 0..1 : 32-col N block
    const int g    = lane >> 2;
    const int tg   = lane & 3;

    const __nv_bfloat16* Arow = g_xbf + (size_t)blockIdx.y * BM * DIN;
    const __nv_bfloat16* Brow = g_wbf + (size_t)blockIdx.x * BN * DIN;

    auto load_stage = [&](int stage, int chunk) {
        const int k0 = chunk * BK;            // bf16 elements (64 bytes)
        const uint32_t base = smem_base + stage * STAGE_BYTES;
        #pragma unroll
        for (int j = 0; j < 3; j++) {
            const int v   = tid + j * 256;
            const int r   = v >> 2;
            const int c16 = (v & 3) * 16;     // byte offset within 64B row
            if (r < BM) {
                CP_ASYNC16(base + r * ROW_PITCH + c16,
                           reinterpret_cast<const char*>(Arow + (size_t)r * DIN + k0) + c16);
            } else {
                const int r2 = r - BM;
                CP_ASYNC16(base + A_STAGE + r2 * ROW_PITCH + c16,
                           reinterpret_cast<const char*>(Brow + (size_t)r2 * DIN + k0) + c16);
            }
        }
    };

    float acc[2][4][4];
    #pragma unroll
    for (int mi = 0; mi < 2; mi++)
        #pragma unroll
        for (int ni = 0; ni < 4; ni++)
            #pragma unroll
            for (int q = 0; q < 4; q++) acc[mi][ni][q] = 0.f;

    #pragma unroll
    for (int s = 0; s < STAGES - 1; s++) { load_stage(s, s); CP_ASYNC_COMMIT(); }

    // ldmatrix per-lane base addresses (validated: rel_err = 0 in R5)
    const uint32_t aOff = (uint32_t)(wm * 32 + (lane & 15)) * ROW_PITCH + ((lane >> 4) * 16);
    const uint32_t bOff = (uint32_t)(wn * 32 + (lane & 7) + ((lane >> 4) << 3)) * ROW_PITCH
                          + ((lane & 8) ? 16u : 0u);

    for (int c = 0; c < NCHUNKS; c++) {
        CP_ASYNC_WAIT(STAGES - 2);
        __syncthreads();
        if (c + STAGES - 1 < NCHUNKS) load_stage((c + STAGES - 1) % STAGES, c + STAGES - 1);
        CP_ASYNC_COMMIT();

        const uint32_t sA = smem_base + (c % STAGES) * STAGE_BYTES;
        const uint32_t sB = sA + A_STAGE;
        #pragma unroll
        for (int ks = 0; ks < 2; ks++) {      // k16 step = 32 bytes
            const uint32_t ko = ks * 32;
            uint32_t a[2][4], b[4][2];
            #pragma unroll
            for (int mi = 0; mi < 2; mi++)
                LDSM_X4(a[mi][0], a[mi][1], a[mi][2], a[mi][3], sA + aOff + mi * 16 * ROW_PITCH + ko);
            #pragma unroll
            for (int np = 0; np < 2; np++)
                LDSM_X4(b[2 * np][0], b[2 * np][1], b[2 * np + 1][0], b[2 * np + 1][1],
                        sB + bOff + np * 16 * ROW_PITCH + ko);
            #pragma unroll
            for (int mi = 0; mi < 2; mi++)
                #pragma unroll
                for (int ni = 0; ni < 4; ni++)
                    hmma_16816(acc[mi][ni], a[mi][0], a[mi][1], a[mi][2], a[mi][3], b[ni][0], b[ni][1]);
        }
    }

    // -------- epilogue: + bias, float2 stores --------
    const int gm0 = blockIdx.y * BM + wm * 32;
    const int gn0 = blockIdx.x * BN + wn * 32;
    #pragma unroll
    for (int ni = 0; ni < 4; ni++) {
        const int col = gn0 + ni * 8 + tg * 2;
        const float2 bb = *reinterpret_cast<const float2*>(bias + col);
        #pragma unroll
        for (int mi = 0; mi < 2; mi++) {
            const int row0 = gm0 + mi * 16 + g;
            float2 o0, o1;
            o0.x = acc[mi][ni][0] + bb.x;
            o0.y = acc[mi][ni][1] + bb.y;
            o1.x = acc[mi][ni][2] + bb.x;
            o1.y = acc[mi][ni][3] + bb.y;
            *reinterpret_cast<float2*>(out + (size_t)row0 * DOUT + col)       = o0;
            *reinterpret_cast<float2*>(out + (size_t)(row0 + 8) * DOUT + col) = o1;
        }
    }
}

// ---------------- launch ----------------
extern "C" void kernel_launch(void* const* d_in, const int* in_sizes, int n_in,
                              void* d_out, int out_size) {
    const float* x    = (const float*)d_in[0];   // [4,2048,2048] fp32
    const float* w    = (const float*)d_in[1];   // [2048,2048] fp32
    const float* xs   = (const float*)d_in[2];   // scalar fp32
    const float* bias = (const float*)d_in[3];   // [2048] fp32
    float* out = (float*)d_out;

    prep_kernel<<<QX_BLOCKS + 1024, 256>>>(x, w, xs);

    static int configured = 0;
    if (!configured) {
        cudaFuncSetAttribute(gemm_bf16_kernel, cudaFuncAttributeMaxDynamicSharedMemorySize, SMEM_TOTAL);
        configured = 1;
    }
    gemm_bf16_kernel<<<dim3(DOUT / BN, MTOT / BM), NTHREADS, SMEM_TOTAL>>>(bias, out);
}

// round 7
// speedup vs baseline: 2.5738x; 1.0606x over previous
#include <cuda_runtime.h>
#include <cuda_bf16.h>
#include <cstdint>

#define DIN   2048
#define DOUT  2048
#define MTOT  8192

// ---------------- scratch (static device globals; no allocation) ----------------
__device__ __nv_bfloat16  g_xbf[(size_t)MTOT * DIN];   // x quantized, [M][K] bf16
__device__ __nv_bfloat16  g_wbf[(size_t)DOUT * DIN];   // W^T as bf16, [N][K] bf16

// ---------------- helpers ----------------
__device__ __forceinline__ uint32_t smem_u32(const void* p) {
    uint32_t a;
    asm("{ .reg .u64 t; cvta.to.shared.u64 t, %1; cvt.u32.u64 %0, t; }" : "=r"(a) : "l"(p));
    return a;
}

#define CP_ASYNC16(dst, src) \
    asm volatile("cp.async.cg.shared.global [%0], [%1], 16;" :: "r"(dst), "l"(src) : "memory")
#define CP_ASYNC_COMMIT() asm volatile("cp.async.commit_group;" ::: "memory")
#define CP_ASYNC_WAIT(n)  asm volatile("cp.async.wait_group %0;" :: "n"(n) : "memory")

#define LDSM_X4(r0, r1, r2, r3, addr) \
    asm volatile("ldmatrix.sync.aligned.m8n8.x4.shared.b16 {%0,%1,%2,%3}, [%4];" \
                 : "=r"(r0), "=r"(r1), "=r"(r2), "=r"(r3) : "r"(addr))

__device__ __forceinline__ void hmma_16816(float* c, uint32_t a0, uint32_t a1, uint32_t a2, uint32_t a3,
                                           uint32_t b0, uint32_t b1) {
    asm volatile(
        "mma.sync.aligned.m16n8k16.row.col.f32.bf16.bf16.f32 "
        "{%0,%1,%2,%3}, {%4,%5,%6,%7}, {%8,%9}, {%0,%1,%2,%3};"
        : "+f"(c[0]), "+f"(c[1]), "+f"(c[2]), "+f"(c[3])
        : "r"(a0), "r"(a1), "r"(a2), "r"(a3), "r"(b0), "r"(b1));
}

// ---------------- fused pre-pass: quantize x -> bf16 AND transpose W -> bf16 ----------------
#define QX_BLOCKS 4096
__global__ void prep_kernel(const float* __restrict__ x, const float* __restrict__ w,
                            const float* __restrict__ scale_p) {
    if (blockIdx.x < QX_BLOCKS) {
        const float inv_s = 1.0f / fmaxf(scale_p[0], 1e-8f);
        const int i = blockIdx.x * blockDim.x + threadIdx.x;   // 0 .. M*K/16-1
        const float4* xin = reinterpret_cast<const float4*>(x) + (size_t)i * 4;
        uint32_t bfp[8];
        #pragma unroll
        for (int j = 0; j < 4; j++) {
            float4 v = xin[j];
            float f0 = fminf(fmaxf(rintf(v.x * inv_s), -127.f), 127.f);
            float f1 = fminf(fmaxf(rintf(v.y * inv_s), -127.f), 127.f);
            float f2 = fminf(fmaxf(rintf(v.z * inv_s), -127.f), 127.f);
            float f3 = fminf(fmaxf(rintf(v.w * inv_s), -127.f), 127.f);
            __nv_bfloat162 p0 = __floats2bfloat162_rn(f0, f1);
            __nv_bfloat162 p1 = __floats2bfloat162_rn(f2, f3);
            bfp[2 * j]     = *reinterpret_cast<uint32_t*>(&p0);
            bfp[2 * j + 1] = *reinterpret_cast<uint32_t*>(&p1);
        }
        uint4* bo = reinterpret_cast<uint4*>(g_xbf) + (size_t)i * 2;
        bo[0] = make_uint4(bfp[0], bfp[1], bfp[2], bfp[3]);
        bo[1] = make_uint4(bfp[4], bfp[5], bfp[6], bfp[7]);
    } else {
        __shared__ float t[128][33];     // [k][n]
        const int bid = blockIdx.x - QX_BLOCKS;        // 0..1023
        const int bx = (bid & 63) * 32;                // n tile
        const int by = (bid >> 6) * 128;               // k tile
        const int tx = threadIdx.x & 31;
        const int ty = threadIdx.x >> 5;               // 0..7
        #pragma unroll
        for (int i = ty; i < 128; i += 8)
            t[i][tx] = w[(size_t)(by + i) * DOUT + bx + tx];   // coalesced reads
        __syncthreads();
        #pragma unroll
        for (int r = 0; r < 4; r++) {
            const int n = ty + r * 8;
            __nv_bfloat162 p0 = __floats2bfloat162_rn(t[tx * 4 + 0][n], t[tx * 4 + 1][n]);
            __nv_bfloat162 p1 = __floats2bfloat162_rn(t[tx * 4 + 2][n], t[tx * 4 + 3][n]);
            uint2 bo;
            bo.x = *reinterpret_cast<uint32_t*>(&p0);
            bo.y = *reinterpret_cast<uint32_t*>(&p1);
            *reinterpret_cast<uint2*>(&g_wbf[(size_t)(bx + n) * DIN + by + tx * 4]) = bo;
        }
    }
}

// ---------------- GEMM: out[M,N] = xbf @ wbf^T + bias (bf16 HMMA, 128x128x32, warp 32x64, occ 2) ----------------
#define BM 128
#define BN 128
#define BK 32                                // bf16 elements = 64 bytes per row-chunk
#define STAGES 4
#define NTHREADS 256
#define NCHUNKS (DIN / BK)                   // 64

#define ROW_PITCH 80                         // 64B data + 16B pad: LDSM phases conflict-free
#define A_STAGE   (BM * ROW_PITCH)           // 10240
#define B_STAGE   (BN * ROW_PITCH)           // 10240
#define STAGE_BYTES (A_STAGE + B_STAGE)      // 20480
#define SMEM_TOTAL (STAGES * STAGE_BYTES)    // 81920

__global__ void __launch_bounds__(NTHREADS, 2) gemm_bf16_kernel(const float* __restrict__ bias,
                                                                float* __restrict__ out) {
    extern __shared__ __align__(128) char smem[];
    const uint32_t smem_base = smem_u32(smem);
    const int tid  = threadIdx.x;
    const int wid  = tid >> 5;
    const int lane = tid & 31;
    const int wm   = wid >> 1;        // 0..3 : 32-row M block
    const int wn   = wid & 1;         // 0..1 : 64-col N block
    const int g    = lane >> 2;
    const int tg   = lane & 3;

    const __nv_bfloat16* Arow = g_xbf + (size_t)blockIdx.y * BM * DIN;
    const __nv_bfloat16* Brow = g_wbf + (size_t)blockIdx.x * BN * DIN;

    // 256 rows x 4 vecs(16B) = 1024 vecs / 256 thr = 4 each
    auto load_stage = [&](int stage, int chunk) {
        const int k0 = chunk * BK;            // bf16 elements (64 bytes)
        const uint32_t base = smem_base + stage * STAGE_BYTES;
        #pragma unroll
        for (int j = 0; j < 4; j++) {
            const int v   = tid + j * 256;
            const int r   = v >> 2;
            const int c16 = (v & 3) * 16;     // byte offset within 64B row
            if (r < BM) {
                CP_ASYNC16(base + r * ROW_PITCH + c16,
                           reinterpret_cast<const char*>(Arow + (size_t)r * DIN + k0) + c16);
            } else {
                const int r2 = r - BM;
                CP_ASYNC16(base + A_STAGE + r2 * ROW_PITCH + c16,
                           reinterpret_cast<const char*>(Brow + (size_t)r2 * DIN + k0) + c16);
            }
        }
    };

    float acc[2][8][4];
    #pragma unroll
    for (int mi = 0; mi < 2; mi++)
        #pragma unroll
        for (int ni = 0; ni < 8; ni++)
            #pragma unroll
            for (int q = 0; q < 4; q++) acc[mi][ni][q] = 0.f;

    #pragma unroll
    for (int s = 0; s < STAGES - 1; s++) { load_stage(s, s); CP_ASYNC_COMMIT(); }

    // ldmatrix per-lane base addresses (mapping validated across R5/R6, rel_err = 0)
    const uint32_t aOff = (uint32_t)(wm * 32 + (lane & 15)) * ROW_PITCH + ((lane >> 4) * 16);
    const uint32_t bOff = (uint32_t)(wn * 64 + (lane & 7) + ((lane >> 4) << 3)) * ROW_PITCH
                          + ((lane & 8) ? 16u : 0u);

    for (int c = 0; c < NCHUNKS; c++) {
        CP_ASYNC_WAIT(STAGES - 2);
        __syncthreads();
        if (c + STAGES - 1 < NCHUNKS) load_stage((c + STAGES - 1) % STAGES, c + STAGES - 1);
        CP_ASYNC_COMMIT();

        const uint32_t sA = smem_base + (c % STAGES) * STAGE_BYTES;
        const uint32_t sB = sA + A_STAGE;
        #pragma unroll
        for (int ks = 0; ks < 2; ks++) {      // k16 step = 32 bytes
            const uint32_t ko = ks * 32;
            uint32_t a[2][4], b[8][2];
            #pragma unroll
            for (int mi = 0; mi < 2; mi++)
                LDSM_X4(a[mi][0], a[mi][1], a[mi][2], a[mi][3], sA + aOff + mi * 16 * ROW_PITCH + ko);
            #pragma unroll
            for (int np = 0; np < 4; np++)
                LDSM_X4(b[2 * np][0], b[2 * np][1], b[2 * np + 1][0], b[2 * np + 1][1],
                        sB + bOff + np * 16 * ROW_PITCH + ko);
            #pragma unroll
            for (int mi = 0; mi < 2; mi++)
                #pragma unroll
                for (int ni = 0; ni < 8; ni++)
                    hmma_16816(acc[mi][ni], a[mi][0], a[mi][1], a[mi][2], a[mi][3], b[ni][0], b[ni][1]);
        }
    }

    // -------- epilogue: + bias, float2 stores --------
    const int gm0 = blockIdx.y * BM + wm * 32;
    const int gn0 = blockIdx.x * BN + wn * 64;
    #pragma unroll
    for (int ni = 0; ni < 8; ni++) {
        const int col = gn0 + ni * 8 + tg * 2;
        const float2 bb = *reinterpret_cast<const float2*>(bias + col);
        #pragma unroll
        for (int mi = 0; mi < 2; mi++) {
            const int row0 = gm0 + mi * 16 + g;
            float2 o0, o1;
            o0.x = acc[mi][ni][0] + bb.x;
            o0.y = acc[mi][ni][1] + bb.y;
            o1.x = acc[mi][ni][2] + bb.x;
            o1.y = acc[mi][ni][3] + bb.y;
            *reinterpret_cast<float2*>(out + (size_t)row0 * DOUT + col)       = o0;
            *reinterpret_cast<float2*>(out + (size_t)(row0 + 8) * DOUT + col) = o1;
        }
    }
}

// ---------------- launch ----------------
extern "C" void kernel_launch(void* const* d_in, const int* in_sizes, int n_in,
                              void* d_out, int out_size) {
    const float* x    = (const float*)d_in[0];   // [4,2048,2048] fp32
    const float* w    = (const float*)d_in[1];   // [2048,2048] fp32
    const float* xs   = (const float*)d_in[2];   // scalar fp32
    const float* bias = (const float*)d_in[3];   // [2048] fp32
    float* out = (float*)d_out;

    prep_kernel<<<QX_BLOCKS + 1024, 256>>>(x, w, xs);

    static int configured = 0;
    if (!configured) {
        cudaFuncSetAttribute(gemm_bf16_kernel, cudaFuncAttributeMaxDynamicSharedMemorySize, SMEM_TOTAL);
        configured = 1;
    }
    gemm_bf16_kernel<<<dim3(DOUT / BN, MTOT / BM), NTHREADS, SMEM_TOTAL>>>(bias, out);
}

// round 8
// speedup vs baseline: 3.1953x; 1.2415x over previous
#include <cuda_runtime.h>
#include <cuda_bf16.h>
#include <cstdint>

#define DIN   2048
#define DOUT  2048
#define MTOT  8192

// ---------------- scratch (static device globals; no allocation) ----------------
__device__ __nv_bfloat16  g_xbf[(size_t)MTOT * DIN];   // x quantized, [M][K] bf16
__device__ __nv_bfloat16  g_wbf[(size_t)DOUT * DIN];   // W^T as bf16, [N][K] bf16

// ---------------- helpers ----------------
__device__ __forceinline__ uint32_t smem_u32(const void* p) {
    uint32_t a;
    asm("{ .reg .u64 t; cvta.to.shared.u64 t, %1; cvt.u32.u64 %0, t; }" : "=r"(a) : "l"(p));
    return a;
}

#define CP_ASYNC16(dst, src) \
    asm volatile("cp.async.cg.shared.global [%0], [%1], 16;" :: "r"(dst), "l"(src) : "memory")
#define CP_ASYNC_COMMIT() asm volatile("cp.async.commit_group;" ::: "memory")
#define CP_ASYNC_WAIT(n)  asm volatile("cp.async.wait_group %0;" :: "n"(n) : "memory")

#define LDSM_X4(r0, r1, r2, r3, addr) \
    asm volatile("ldmatrix.sync.aligned.m8n8.x4.shared.b16 {%0,%1,%2,%3}, [%4];" \
                 : "=r"(r0), "=r"(r1), "=r"(r2), "=r"(r3) : "r"(addr))

__device__ __forceinline__ void hmma_16816(float* c, uint32_t a0, uint32_t a1, uint32_t a2, uint32_t a3,
                                           uint32_t b0, uint32_t b1) {
    asm volatile(
        "mma.sync.aligned.m16n8k16.row.col.f32.bf16.bf16.f32 "
        "{%0,%1,%2,%3}, {%4,%5,%6,%7}, {%8,%9}, {%0,%1,%2,%3};"
        : "+f"(c[0]), "+f"(c[1]), "+f"(c[2]), "+f"(c[3])
        : "r"(a0), "r"(a1), "r"(a2), "r"(a3), "r"(b0), "r"(b1));
}

// ---------------- fused pre-pass: quantize x -> bf16 AND transpose W -> bf16 ----------------
#define QX_BLOCKS 4096
__global__ void prep_kernel(const float* __restrict__ x, const float* __restrict__ w,
                            const float* __restrict__ scale_p) {
    if (blockIdx.x < QX_BLOCKS) {
        const float inv_s = 1.0f / fmaxf(scale_p[0], 1e-8f);
        const int i = blockIdx.x * blockDim.x + threadIdx.x;   // 0 .. M*K/16-1
        const float4* xin = reinterpret_cast<const float4*>(x) + (size_t)i * 4;
        uint32_t bfp[8];
        #pragma unroll
        for (int j = 0; j < 4; j++) {
            float4 v = xin[j];
            float f0 = fminf(fmaxf(rintf(v.x * inv_s), -127.f), 127.f);
            float f1 = fminf(fmaxf(rintf(v.y * inv_s), -127.f), 127.f);
            float f2 = fminf(fmaxf(rintf(v.z * inv_s), -127.f), 127.f);
            float f3 = fminf(fmaxf(rintf(v.w * inv_s), -127.f), 127.f);
            __nv_bfloat162 p0 = __floats2bfloat162_rn(f0, f1);
            __nv_bfloat162 p1 = __floats2bfloat162_rn(f2, f3);
            bfp[2 * j]     = *reinterpret_cast<uint32_t*>(&p0);
            bfp[2 * j + 1] = *reinterpret_cast<uint32_t*>(&p1);
        }
        uint4* bo = reinterpret_cast<uint4*>(g_xbf) + (size_t)i * 2;
        bo[0] = make_uint4(bfp[0], bfp[1], bfp[2], bfp[3]);
        bo[1] = make_uint4(bfp[4], bfp[5], bfp[6], bfp[7]);
    } else {
        __shared__ float t[128][33];     // [k][n]
        const int bid = blockIdx.x - QX_BLOCKS;        // 0..1023
        const int bx = (bid & 63) * 32;                // n tile
        const int by = (bid >> 6) * 128;               // k tile
        const int tx = threadIdx.x & 31;
        const int ty = threadIdx.x >> 5;               // 0..7
        #pragma unroll
        for (int i = ty; i < 128; i += 8)
            t[i][tx] = w[(size_t)(by + i) * DOUT + bx + tx];   // coalesced reads
        __syncthreads();
        #pragma unroll
        for (int r = 0; r < 4; r++) {
            const int n = ty + r * 8;
            __nv_bfloat162 p0 = __floats2bfloat162_rn(t[tx * 4 + 0][n], t[tx * 4 + 1][n]);
            __nv_bfloat162 p1 = __floats2bfloat162_rn(t[tx * 4 + 2][n], t[tx * 4 + 3][n]);
            uint2 bo;
            bo.x = *reinterpret_cast<uint32_t*>(&p0);
            bo.y = *reinterpret_cast<uint32_t*>(&p1);
            *reinterpret_cast<uint2*>(&g_wbf[(size_t)(bx + n) * DIN + by + tx * 4]) = bo;
        }
    }
}

// ---------------- GEMM: 128x128x64 chunks, swizzled 128B rows, warp 32x64, occ 2 ----------------
#define BM 128
#define BN 128
#define BK 64                                // bf16 elements = 128 bytes per row-chunk
#define STAGES 3
#define NTHREADS 256
#define NCHUNKS (DIN / BK)                   // 32

#define A_STAGE   (BM * 128)                 // 16384
#define B_STAGE   (BN * 128)                 // 16384
#define STAGE_BYTES (A_STAGE + B_STAGE)      // 32768
#define SMEM_TOTAL (STAGES * STAGE_BYTES)    // 98304

__global__ void __launch_bounds__(NTHREADS, 2) gemm_bf16_kernel(const float* __restrict__ bias,
                                                                float* __restrict__ out) {
    extern __shared__ __align__(1024) char smem[];
    const uint32_t smem_base = smem_u32(smem);
    const int tid  = threadIdx.x;
    const int wid  = tid >> 5;
    const int lane = tid & 31;
    const int wm   = wid >> 1;        // 0..3 : 32-row M block
    const int wn   = wid & 1;         // 0..1 : 64-col N block
    const int g    = lane >> 2;
    const int tg   = lane & 3;

    const __nv_bfloat16* Arow = g_xbf + (size_t)blockIdx.y * BM * DIN;
    const __nv_bfloat16* Brow = g_wbf + (size_t)blockIdx.x * BN * DIN;

    // 256 rows x 8 vecs(16B) = 2048 vecs / 256 thr = 8 each; swizzle: c16 ^= (row & 7)
    auto load_stage = [&](int stage, int chunk) {
        const int k0 = chunk * BK;            // bf16 elements (128 bytes)
        const uint32_t base = smem_base + stage * STAGE_BYTES;
        #pragma unroll
        for (int j = 0; j < 8; j++) {
            const int v  = tid + j * 256;
            const int r  = v >> 3;
            const int cc = v & 7;
            const uint32_t dst_off = (uint32_t)(r & 127) * 128 + ((cc ^ (r & 7)) << 4);
            if (r < BM) {
                CP_ASYNC16(base + dst_off,
                           reinterpret_cast<const char*>(Arow + (size_t)r * DIN + k0) + cc * 16);
            } else {
                CP_ASYNC16(base + A_STAGE + dst_off,
                           reinterpret_cast<const char*>(Brow + (size_t)(r - BM) * DIN + k0) + cc * 16);
            }
        }
    };

    float acc[2][8][4];
    #pragma unroll
    for (int mi = 0; mi < 2; mi++)
        #pragma unroll
        for (int ni = 0; ni < 8; ni++)
            #pragma unroll
            for (int q = 0; q < 4; q++) acc[mi][ni][q] = 0.f;

    #pragma unroll
    for (int s = 0; s < STAGES - 1; s++) { load_stage(s, s); CP_ASYNC_COMMIT(); }

    // per-lane row/col components for swizzled LDSM addressing
    const int aRowL = wm * 32 + (lane & 15);          // + mi*16
    const int aColL = lane >> 4;                      // + ks*2
    const int bRowL = wn * 64 + (lane & 7) + ((lane >> 4) << 3);  // + np*16
    const int bColL = (lane & 8) ? 1 : 0;             // + ks*2

    for (int c = 0; c < NCHUNKS; c++) {
        CP_ASYNC_WAIT(STAGES - 2);
        __syncthreads();
        if (c + STAGES - 1 < NCHUNKS) load_stage((c + STAGES - 1) % STAGES, c + STAGES - 1);
        CP_ASYNC_COMMIT();

        const uint32_t sA = smem_base + (c % STAGES) * STAGE_BYTES;
        const uint32_t sB = sA + A_STAGE;
        #pragma unroll
        for (int ks = 0; ks < 4; ks++) {      // k16 step = 2 16B-cols
            uint32_t a[2][4], b[8][2];
            #pragma unroll
            for (int mi = 0; mi < 2; mi++) {
                const int r = aRowL + mi * 16;
                const int ccol = (aColL + ks * 2) ^ (r & 7);
                LDSM_X4(a[mi][0], a[mi][1], a[mi][2], a[mi][3],
                        sA + (uint32_t)r * 128 + (ccol << 4));
            }
            #pragma unroll
            for (int np = 0; np < 4; np++) {
                const int r = bRowL + np * 16;
                const int ccol = (bColL + ks * 2) ^ (r & 7);
                LDSM_X4(b[2 * np][0], b[2 * np][1], b[2 * np + 1][0], b[2 * np + 1][1],
                        sB + (uint32_t)r * 128 + (ccol << 4));
            }
            #pragma unroll
            for (int mi = 0; mi < 2; mi++)
                #pragma unroll
                for (int ni = 0; ni < 8; ni++)
                    hmma_16816(acc[mi][ni], a[mi][0], a[mi][1], a[mi][2], a[mi][3], b[ni][0], b[ni][1]);
        }
    }

    // -------- epilogue: + bias, float2 stores --------
    const int gm0 = blockIdx.y * BM + wm * 32;
    const int gn0 = blockIdx.x * BN + wn * 64;
    #pragma unroll
    for (int ni = 0; ni < 8; ni++) {
        const int col = gn0 + ni * 8 + tg * 2;
        const float2 bb = *reinterpret_cast<const float2*>(bias + col);
        #pragma unroll
        for (int mi = 0; mi < 2; mi++) {
            const int row0 = gm0 + mi * 16 + g;
            float2 o0, o1;
            o0.x = acc[mi][ni][0] + bb.x;
            o0.y = acc[mi][ni][1] + bb.y;
            o1.x = acc[mi][ni][2] + bb.x;
            o1.y = acc[mi][ni][3] + bb.y;
            *reinterpret_cast<float2*>(out + (size_t)row0 * DOUT + col)       = o0;
            *reinterpret_cast<float2*>(out + (size_t)(row0 + 8) * DOUT + col) = o1;
        }
    }
}

// ---------------- launch ----------------
extern "C" void kernel_launch(void* const* d_in, const int* in_sizes, int n_in,
                              void* d_out, int out_size) {
    const float* x    = (const float*)d_in[0];   // [4,2048,2048] fp32
    const float* w    = (const float*)d_in[1];   // [2048,2048] fp32
    const float* xs   = (const float*)d_in[2];   // scalar fp32
    const float* bias = (const float*)d_in[3];   // [2048] fp32
    float* out = (float*)d_out;

    prep_kernel<<<QX_BLOCKS + 1024, 256>>>(x, w, xs);

    static int configured = 0;
    if (!configured) {
        cudaFuncSetAttribute(gemm_bf16_kernel, cudaFuncAttributeMaxDynamicSharedMemorySize, SMEM_TOTAL);
        configured = 1;
    }
    gemm_bf16_kernel<<<dim3(DOUT / BN, MTOT / BM), NTHREADS, SMEM_TOTAL>>>(bias, out);
}